// round 11
// baseline (speedup 1.0000x reference)
#include <cuda_runtime.h>
#include <cuda_bf16.h>
#include <cstdint>

namespace {
constexpr int H=448, Wd=608, K=32, Bn=2, TPB=512, PXT=128, WT=5;
constexpr int XS=72;                        // bf16 row stride (144B = 9*16B)
constexpr int XSPL=128*XS*2;                // 18432 per activation split
constexpr int WSPL=64*XS*2;                 // 9216 per 64-row weight split
constexpr int W3SPL=32*XS*2;                // 4608
constexpr float TAU=1e-3f;                  // near-tie gap threshold (abs)

constexpr int SM_B1=0, SM_B2=256, SM_B3=512, SM_BR=640;
constexpr int SM_PV1=1024;                  // [2][128] f32 top1 val
constexpr int SM_PV2=2048;                  // [2][128] f32 top2 val
constexpr int SM_PI1=3072;                  // [2][128] i32 top1 idx
constexpr int SM_NF=4096;                   // flag count
constexpr int SM_FL=4224;                   // flag list [128]
constexpr int SM_SCR=4864;                  // 16 warps x 128 f32 scratch (8192)
constexpr int SM_XF=13312;                  // x fp32 [128][65] (33280)
constexpr int SM_X =46592;                  // X splits x2 (Y1 overlays after Dr)
constexpr int SM_Y0=SM_X+2*XSPL;            // 83456 (Dr f32 overlay after L2)
constexpr int SM_W1=SM_Y0+2*XSPL;           // 120320
constexpr int SM_W2=SM_W1+2*WSPL;           // 138752
constexpr int SM_W3=SM_W2+2*WSPL;           // 157184
constexpr int SM_WR=SM_W3+2*W3SPL;          // 166400
constexpr int SMEM_BYTES=SM_WR+2*WSPL;      // 184832
constexpr int SM_DR=SM_Y0;
constexpr int DRS=66;
}

__device__ __forceinline__ float lrelu(float v){ return v>=0.f ? v : 0.01f*v; }
__device__ __forceinline__ uint32_t smem_u32(const void* p){
    uint32_t a;
    asm("{ .reg .u64 t; cvta.to.shared.u64 t, %1; cvt.u32.u64 %0, t; }" : "=r"(a) : "l"(p));
    return a;
}
__device__ __forceinline__ void sts32(uint32_t a, uint32_t v){
    asm volatile("st.shared.b32 [%0], %1;" :: "r"(a), "r"(v) : "memory");
}
__device__ __forceinline__ void ldsm4(uint32_t addr, uint32_t* r){
    asm volatile("ldmatrix.sync.aligned.m8n8.x4.shared.b16 {%0,%1,%2,%3}, [%4];"
                 : "=r"(r[0]), "=r"(r[1]), "=r"(r[2]), "=r"(r[3]) : "r"(addr));
}
__device__ __forceinline__ void mma_bf16(float d[4], const uint32_t a[4], uint32_t b0, uint32_t b1){
    asm volatile("mma.sync.aligned.m16n8k16.row.col.f32.bf16.bf16.f32 "
                 "{%0,%1,%2,%3},{%4,%5,%6,%7},{%8,%9},{%0,%1,%2,%3};"
                 : "+f"(d[0]), "+f"(d[1]), "+f"(d[2]), "+f"(d[3])
                 : "r"(a[0]), "r"(a[1]), "r"(a[2]), "r"(a[3]), "r"(b0), "r"(b1));
}
__device__ __forceinline__ uint32_t hb(__nv_bfloat16 h){
    return (uint32_t)reinterpret_cast<const uint16_t&>(h);
}
__device__ __forceinline__ void split2pair(float a, float b, uint32_t s[2]){
    __nv_bfloat16 a0=__float2bfloat16_rn(a);
    __nv_bfloat16 a1=__float2bfloat16_rn(a-__bfloat162float(a0));
    __nv_bfloat16 b0=__float2bfloat16_rn(b);
    __nv_bfloat16 b1=__float2bfloat16_rn(b-__bfloat162float(b0));
    s[0]=hb(a0)|(hb(b0)<<16); s[1]=hb(a1)|(hb(b1)<<16);
}

// 2-split 3-pass emulated GEMM; warp tile 32px x 16n. aB/bB lane-resolved bases.
__device__ __forceinline__ void gemm3(uint32_t aB, uint32_t bB, int bSpl, float D[4][4]){
    #pragma unroll
    for(int i=0;i<4;++i){ D[i][0]=D[i][1]=D[i][2]=D[i][3]=0.f; }
    constexpr int PA[3]={0,0,1};
    constexpr int PB[3]={0,1,0};
    #pragma unroll 1
    for(int ks=0;ks<4;++ks){
        uint32_t a[2][2][4];
        #pragma unroll
        for(int s=0;s<2;++s){
            ldsm4(aB+s*XSPL+ks*32, a[s][0]);
            ldsm4(aB+s*XSPL+16*XS*2+ks*32, a[s][1]);
        }
        uint32_t bf[2][4];
        #pragma unroll
        for(int s=0;s<2;++s) ldsm4(bB+s*bSpl+ks*32, bf[s]);
        #pragma unroll
        for(int p=0;p<3;++p)
            #pragma unroll
            for(int mt=0;mt<2;++mt)
                #pragma unroll
                for(int nt=0;nt<2;++nt)
                    mma_bf16(D[mt*2+nt], a[PA[p]][mt],
                             bf[PB[p]][nt*2], bf[PB[p]][nt*2+1]);
    }
}

// bias + lrelu + 2-split bf16 store; warp covers 32px x 16n
__device__ __forceinline__ void epi2(float D[4][4], const float* __restrict__ bias,
                                     uint32_t outB, int wm, int wn, int lane){
    const int g=lane>>2, c2=2*(lane&3);
    #pragma unroll
    for(int mt=0;mt<2;++mt)
        #pragma unroll
        for(int nt=0;nt<2;++nt){
            const int n0=wn*16+nt*8+c2;
            const float bv0=bias[n0], bv1=bias[n0+1];
            const float* d=D[mt*2+nt];
            uint32_t s[2];
            const uint32_t a0=outB+((wm*32+mt*16+g)*XS+n0)*2;
            split2pair(lrelu(d[0]+bv0), lrelu(d[1]+bv1), s);
            sts32(a0,s[0]); sts32(a0+XSPL,s[1]);
            const uint32_t a1=a0+8*XS*2;
            split2pair(lrelu(d[2]+bv0), lrelu(d[3]+bv1), s);
            sts32(a1,s[0]); sts32(a1+XSPL,s[1]);
        }
}

__global__ void __launch_bounds__(TPB,1)
reg1stage_emu(const float* __restrict__ x,
              const float* __restrict__ W1g, const float* __restrict__ b1g,
              const float* __restrict__ W2g, const float* __restrict__ b2g,
              const float* __restrict__ W3g, const float* __restrict__ b3g,
              const float* __restrict__ Wr,  const float* __restrict__ br,
              float* __restrict__ out)
{
    extern __shared__ char smem[];
    const uint32_t sb = smem_u32(smem);
    float* smf = reinterpret_cast<float*>(smem);
    float* sV1 = reinterpret_cast<float*>(smem+SM_PV1);
    float* sV2 = reinterpret_cast<float*>(smem+SM_PV2);
    int*   sI1 = reinterpret_cast<int*>(smem+SM_PI1);
    int*   sNF = reinterpret_cast<int*>(smem+SM_NF);
    int*   sFL = reinterpret_cast<int*>(smem+SM_FL);
    float* scr = reinterpret_cast<float*>(smem+SM_SCR);
    float* xf  = reinterpret_cast<float*>(smem+SM_XF);
    const int tid=threadIdx.x, lane=tid&31, warp=tid>>5;
    const int wm=warp>>2, wn=warp&3;        // 4x4 warp grid
    const int h=blockIdx.x, b=blockIdx.y;

    // ---- stage weights: fp32 -> 2 bf16 splits ----
    {
        const float* g1=W1g+h*4096;
        const float* g2=W2g+h*4096;
        #pragma unroll
        for(int i=0;i<4;++i){
            const int p=tid+i*TPB;                 // pair 0..2047
            const int n=p>>5, c0=(p&31)*2;
            uint32_t s[2];
            const float2 v1=*reinterpret_cast<const float2*>(g1+n*64+c0);
            split2pair(v1.x,v1.y,s);
            uint32_t a=sb+SM_W1+(n*XS+c0)*2;
            sts32(a,s[0]); sts32(a+WSPL,s[1]);
            const float2 v2=*reinterpret_cast<const float2*>(g2+n*64+c0);
            split2pair(v2.x,v2.y,s);
            a=sb+SM_W2+(n*XS+c0)*2;
            sts32(a,s[0]); sts32(a+WSPL,s[1]);
        }
        const float* g3=W3g+h*2048;
        #pragma unroll
        for(int i=0;i<2;++i){
            const int p=tid+i*TPB;                 // pair 0..1023
            const int n=p>>5, c0=(p&31)*2;
            uint32_t s[2];
            const float2 v=*reinterpret_cast<const float2*>(g3+n*64+c0);
            split2pair(v.x,v.y,s);
            const uint32_t a=sb+SM_W3+(n*XS+c0)*2;
            sts32(a,s[0]); sts32(a+W3SPL,s[1]);
        }
        // Wr [(h*K+k)][c][2] -> row n=2k+o, col c; 2 splits
        const float* gr=Wr+(size_t)(h*K)*128;
        const int n=tid>>3, k=n>>1, o=n&1;
        #pragma unroll
        for(int j=0;j<4;++j){
            const int c=2*((tid&7)+j*8);
            const float va=gr[k*128+c*2+o];
            const float vb=gr[k*128+(c+1)*2+o];
            uint32_t s[2];
            split2pair(va,vb,s);
            const uint32_t a=sb+SM_WR+(n*XS+c)*2;
            sts32(a,s[0]); sts32(a+WSPL,s[1]);
        }
        if(tid<64){
            smf[SM_B1/4+tid]=b1g[h*64+tid];
            smf[SM_B2/4+tid]=b2g[h*64+tid];
            smf[SM_BR/4+tid]=br[h*64+tid];
        }
        if(tid<32) smf[SM_B3/4+tid]=b3g[h*32+tid];
    }

    const size_t HW=(size_t)H*Wd;
    const float* xbase=x+(size_t)b*64*HW+(size_t)h*Wd;
    const int pix_base=(b*H+h)*Wd;
    const int plane=Bn*H*Wd;
    const float inv_k=1.0f/(float)K;

    // lane-resolved ldmatrix bases
    const uint32_t aRel=((wm*32+(lane&15))*XS+(lane>>4)*8)*2;
    const uint32_t bRel=(((lane>>4)*8+(lane&7))*XS+((lane>>3)&1)*8)*2;
    const uint32_t aX =sb+SM_X +aRel;
    const uint32_t aY0=sb+SM_Y0+aRel;
    const uint32_t bW1=sb+SM_W1+bRel+(wn*16)*XS*2;
    const uint32_t bW2=sb+SM_W2+bRel+(wn*16)*XS*2;
    const uint32_t bW3=sb+SM_W3+bRel+(wn*16)*XS*2;   // valid for wn<2
    const uint32_t bWR=sb+SM_WR+bRel+(wn*16)*XS*2;

    __syncthreads();

    for(int wt=0;wt<WT;++wt){
        const int w0=wt*PXT;

        // ---- stage X: fp32 copy + 2 bf16 splits ----
        {
            if(tid==0) *sNF=0;
            const int px=tid&127, c0=(tid>>7)*16;
            const int wcl=min(w0+px, Wd-1);
            const float* xp=xbase+wcl;
            #pragma unroll
            for(int j=0;j<8;++j){
                const int c=c0+2*j;
                const float va=__ldg(xp+(size_t)c*HW);
                const float vb=__ldg(xp+(size_t)(c+1)*HW);
                xf[px*65+c]=va; xf[px*65+c+1]=vb;
                uint32_t s[2];
                split2pair(va,vb,s);
                const uint32_t a=sb+SM_X+(px*XS+c)*2;
                sts32(a,s[0]); sts32(a+XSPL,s[1]);
            }
        }
        __syncthreads();

        // ---- L1: Y0 = lrelu(X.W1^T+b1) ----
        {
            float D1[4][4];
            gemm3(aX,bW1,WSPL,D1);
            epi2(D1, smf+SM_B1/4, sb+SM_Y0, wm, wn, lane);
        }
        // ---- Dr = X.Wr^T, kept in regs across L2 ----
        float Dr[4][4];
        gemm3(aX,bWR,WSPL,Dr);
        __syncthreads();            // Y0 published; X-split reads done

        // ---- L2: Y1 = lrelu(Y0.W2^T+b2) -> overlays X splits ----
        {
            float D2[4][4];
            gemm3(aY0,bW2,WSPL,D2);
            epi2(D2, smf+SM_B2/4, sb+SM_X, wm, wn, lane);
        }
        __syncthreads();            // Y1 published; Y0 reads done

        // ---- L3 (warps wn<2): cls logits -> per-pixel top-2 partials ----
        if(wn<2){
            float D3[4][4];
            gemm3(aX,bW3,W3SPL,D3);
            const float* b3s=smf+SM_B3/4;
            const int g=lane>>2, c2=2*(lane&3);
            #pragma unroll
            for(int mt=0;mt<2;++mt){
                #pragma unroll
                for(int half=0;half<2;++half){
                    // 4 candidates, ascending class order
                    float v1=-3.402823466e38f, v2=-3.402823466e38f; int i1=0;
                    #pragma unroll
                    for(int nt=0;nt<2;++nt){
                        const int base=wn*16+nt*8+c2;
                        #pragma unroll
                        for(int q=0;q<2;++q){
                            const float v=D3[mt*2+nt][half*2+q]+b3s[base+q];
                            if(v>v1){ v2=v1; v1=v; i1=base+q; }
                            else if(v>v2){ v2=v; }
                        }
                    }
                    #pragma unroll
                    for(int m=1;m<=2;m<<=1){
                        const float u1=__shfl_xor_sync(0xFFFFFFFFu,v1,m);
                        const int   j1=__shfl_xor_sync(0xFFFFFFFFu,i1,m);
                        const float u2=__shfl_xor_sync(0xFFFFFFFFu,v2,m);
                        if(u1>v1 || (u1==v1 && j1<i1)){ v2=fmaxf(v1,u2); v1=u1; i1=j1; }
                        else { v2=fmaxf(u1,v2); }
                    }
                    if((lane&3)==0){
                        const int r=wm*32+mt*16+half*8+g;
                        sV1[wn*128+r]=v1; sV2[wn*128+r]=v2; sI1[wn*128+r]=i1;
                    }
                }
            }
        }
        // ---- spill Dr (f32) into freed Y0 region (all warps) ----
        {
            float* dr=reinterpret_cast<float*>(smem+SM_DR);
            const int g=lane>>2, c2=2*(lane&3);
            #pragma unroll
            for(int mt=0;mt<2;++mt)
                #pragma unroll
                for(int nt=0;nt<2;++nt){
                    const int n0=wn*16+nt*8+c2;
                    const float* d=Dr[mt*2+nt];
                    *reinterpret_cast<float2*>(dr+(wm*32+mt*16+g)*DRS+n0)  =make_float2(d[0],d[1]);
                    *reinterpret_cast<float2*>(dr+(wm*32+mt*16+g+8)*DRS+n0)=make_float2(d[2],d[3]);
                }
        }
        __syncthreads();

        // ---- tail A: merge top-2, flag near-ties, write clear winners ----
        if(tid<128){
            const int px=tid, wc=w0+px;
            if(wc<Wd){
                const float v1a=sV1[px],     v2a=sV2[px];     const int i1a=sI1[px];
                const float v1b=sV1[128+px], v2b=sV2[128+px]; const int i1b=sI1[128+px];
                float top1, sec; int bk;
                if(v1b>v1a){ top1=v1b; bk=i1b; sec=fmaxf(v1a,v2b); }
                else       { top1=v1a; bk=i1a; sec=fmaxf(v1b,v2a); }  // tie -> lower classes ✓
                if(top1-sec < TAU){
                    const int f=atomicAdd(sNF,1);
                    sFL[f]=px;
                } else {
                    const float* dr=reinterpret_cast<const float*>(smem+SM_DR);
                    const float2 dv=*reinterpret_cast<const float2*>(dr+px*DRS+2*bk);
                    const float reg0=lrelu(dv.x+smf[SM_BR/4+2*bk]);
                    const float reg1=lrelu(dv.y+smf[SM_BR/4+2*bk+1]);
                    const int flat=h*K+bk;
                    out[pix_base+wc]      =((float)flat+reg0)*inv_k;
                    out[plane+pix_base+wc]=lrelu(reg1);
                }
            }
        }
        __syncthreads();

        // ---- tail B: exact fp32 recompute for flagged pixels ----
        {
            const int nF=*sNF;
            for(int f=warp; f<nF; f+=16){
                const int px=sFL[f];
                const float* xp=xf+px*65;
                float* y0=scr+warp*128;
                float* y1=y0+64;
                // L1
                #pragma unroll 1
                for(int o=lane;o<64;o+=32){
                    float acc=smf[SM_B1/4+o];
                    const float* wr=W1g+h*4096+o*64;
                    #pragma unroll 1
                    for(int c=0;c<64;++c) acc=fmaf(__ldg(wr+c),xp[c],acc);
                    y0[o]=lrelu(acc);
                }
                __syncwarp();
                // L2
                #pragma unroll 1
                for(int o=lane;o<64;o+=32){
                    float acc=smf[SM_B2/4+o];
                    const float* wr=W2g+h*4096+o*64;
                    #pragma unroll 1
                    for(int c=0;c<64;++c) acc=fmaf(__ldg(wr+c),y0[c],acc);
                    y1[o]=lrelu(acc);
                }
                __syncwarp();
                // L3 + warp argmax (first-max)
                float v=-3.402823466e38f; int idx=lane&31;
                if(lane<32){
                    float acc=smf[SM_B3/4+lane];
                    const float* wr=W3g+h*2048+lane*64;
                    #pragma unroll 1
                    for(int c=0;c<64;++c) acc=fmaf(__ldg(wr+c),y1[c],acc);
                    v=acc;
                }
                #pragma unroll
                for(int m=16;m>=1;m>>=1){
                    const float ov=__shfl_xor_sync(0xFFFFFFFFu,v,m);
                    const int   oi=__shfl_xor_sync(0xFFFFFFFFu,idx,m);
                    if(ov>v || (ov==v && oi<idx)){ v=ov; idx=oi; }
                }
                if(lane==0){
                    const int bk=idx, wc=w0+px;
                    const float* dr=reinterpret_cast<const float*>(smem+SM_DR);
                    const float2 dv=*reinterpret_cast<const float2*>(dr+px*DRS+2*bk);
                    const float reg0=lrelu(dv.x+smf[SM_BR/4+2*bk]);
                    const float reg1=lrelu(dv.y+smf[SM_BR/4+2*bk+1]);
                    const int flat=h*K+bk;
                    out[pix_base+wc]      =((float)flat+reg0)*inv_k;
                    out[plane+pix_base+wc]=lrelu(reg1);
                }
            }
        }
        __syncthreads();            // dr/xf/flags reads done before next tile
    }
}

extern "C" void kernel_launch(void* const* d_in, const int* in_sizes, int n_in,
                              void* d_out, int out_size)
{
    const float* x =(const float*)d_in[0];
    const float* W1=(const float*)d_in[1];
    const float* b1=(const float*)d_in[2];
    const float* W2=(const float*)d_in[3];
    const float* b2=(const float*)d_in[4];
    const float* W3=(const float*)d_in[5];
    const float* b3=(const float*)d_in[6];
    const float* Wr=(const float*)d_in[7];
    const float* br=(const float*)d_in[8];
    float* out=(float*)d_out;

    cudaFuncSetAttribute(reg1stage_emu,
                         cudaFuncAttributeMaxDynamicSharedMemorySize, SMEM_BYTES);
    dim3 grid(H,Bn);
    reg1stage_emu<<<grid,TPB,SMEM_BYTES>>>(x,W1,b1,W2,b2,W3,b3,Wr,br,out);
}

// round 12
// speedup vs baseline: 4.8515x; 4.8515x over previous
#include <cuda_runtime.h>
#include <cuda_bf16.h>
#include <cstdint>

namespace {
constexpr int H=448, Wd=608, K=32, Bn=2, TPB=512, PXT=128, WT=5;
constexpr int XS=72;                        // bf16 row stride (144B = 9*16B)
constexpr int XSPL=128*XS*2;                // 18432 per activation split
constexpr int WSPL=64*XS*2;                 // 9216 per 64-row weight split
constexpr int W3SPL=32*XS*2;                // 4608
constexpr float TAU=2e-4f;                  // near-tie gap threshold (abs)

constexpr int SM_B1=0, SM_B2=256, SM_B3=512, SM_BR=640;
constexpr int SM_PV1=1024;                  // [2][128] f32 top1 val
constexpr int SM_PV2=2048;                  // [2][128] f32 top2 val
constexpr int SM_PI1=3072;                  // [2][128] i32 top1 idx
constexpr int SM_NF=4096;                   // flag count
constexpr int SM_FL=4224;                   // flag list [128]
constexpr int SM_SCR=4864;                  // 16 warps x 128 f32 scratch (8192)
constexpr int SM_XF=13312;                  // x fp32 [128][65] (33280)
constexpr int SM_X =46592;                  // X splits x2 (Y1 overlays after Dr)
constexpr int SM_Y0=SM_X+2*XSPL;            // 83456 (Dr f32 overlay after L2)
constexpr int SM_W1=SM_Y0+2*XSPL;           // 120320
constexpr int SM_W2=SM_W1+2*WSPL;           // 138752
constexpr int SM_W3=SM_W2+2*WSPL;           // 157184
constexpr int SM_WR=SM_W3+2*W3SPL;          // 166400
constexpr int SM_WF1=SM_WR+2*WSPL;          // 184832  fp32 W1 [64][65]
constexpr int SM_WF2=SM_WF1+64*65*4;        // 201472  fp32 W2 [64][65]
constexpr int SM_WF3=SM_WF2+64*65*4;        // 218112  fp32 W3 [32][65]
constexpr int SMEM_BYTES=SM_WF3+32*65*4;    // 226432 (< 227KB cap)
constexpr int SM_DR=SM_Y0;
constexpr int DRS=66;
}

__device__ __forceinline__ float lrelu(float v){ return v>=0.f ? v : 0.01f*v; }
__device__ __forceinline__ uint32_t smem_u32(const void* p){
    uint32_t a;
    asm("{ .reg .u64 t; cvta.to.shared.u64 t, %1; cvt.u32.u64 %0, t; }" : "=r"(a) : "l"(p));
    return a;
}
__device__ __forceinline__ void sts32(uint32_t a, uint32_t v){
    asm volatile("st.shared.b32 [%0], %1;" :: "r"(a), "r"(v) : "memory");
}
__device__ __forceinline__ void ldsm4(uint32_t addr, uint32_t* r){
    asm volatile("ldmatrix.sync.aligned.m8n8.x4.shared.b16 {%0,%1,%2,%3}, [%4];"
                 : "=r"(r[0]), "=r"(r[1]), "=r"(r[2]), "=r"(r[3]) : "r"(addr));
}
__device__ __forceinline__ void mma_bf16(float d[4], const uint32_t a[4], uint32_t b0, uint32_t b1){
    asm volatile("mma.sync.aligned.m16n8k16.row.col.f32.bf16.bf16.f32 "
                 "{%0,%1,%2,%3},{%4,%5,%6,%7},{%8,%9},{%0,%1,%2,%3};"
                 : "+f"(d[0]), "+f"(d[1]), "+f"(d[2]), "+f"(d[3])
                 : "r"(a[0]), "r"(a[1]), "r"(a[2]), "r"(a[3]), "r"(b0), "r"(b1));
}
__device__ __forceinline__ uint32_t hb(__nv_bfloat16 h){
    return (uint32_t)reinterpret_cast<const uint16_t&>(h);
}
__device__ __forceinline__ void split2pair(float a, float b, uint32_t s[2]){
    __nv_bfloat16 a0=__float2bfloat16_rn(a);
    __nv_bfloat16 a1=__float2bfloat16_rn(a-__bfloat162float(a0));
    __nv_bfloat16 b0=__float2bfloat16_rn(b);
    __nv_bfloat16 b1=__float2bfloat16_rn(b-__bfloat162float(b0));
    s[0]=hb(a0)|(hb(b0)<<16); s[1]=hb(a1)|(hb(b1)<<16);
}

// 2-split 3-pass emulated GEMM; warp tile 32px x 16n.
__device__ __forceinline__ void gemm3(uint32_t aB, uint32_t bB, int bSpl, float D[4][4]){
    #pragma unroll
    for(int i=0;i<4;++i){ D[i][0]=D[i][1]=D[i][2]=D[i][3]=0.f; }
    constexpr int PA[3]={0,0,1};
    constexpr int PB[3]={0,1,0};
    #pragma unroll 1
    for(int ks=0;ks<4;++ks){
        uint32_t a[2][2][4];
        #pragma unroll
        for(int s=0;s<2;++s){
            ldsm4(aB+s*XSPL+ks*32, a[s][0]);
            ldsm4(aB+s*XSPL+16*XS*2+ks*32, a[s][1]);
        }
        uint32_t bf[2][4];
        #pragma unroll
        for(int s=0;s<2;++s) ldsm4(bB+s*bSpl+ks*32, bf[s]);
        #pragma unroll
        for(int p=0;p<3;++p)
            #pragma unroll
            for(int mt=0;mt<2;++mt)
                #pragma unroll
                for(int nt=0;nt<2;++nt)
                    mma_bf16(D[mt*2+nt], a[PA[p]][mt],
                             bf[PB[p]][nt*2], bf[PB[p]][nt*2+1]);
    }
}

// bias + lrelu + 2-split bf16 store; warp covers 32px x 16n
__device__ __forceinline__ void epi2(float D[4][4], const float* __restrict__ bias,
                                     uint32_t outB, int wm, int wn, int lane){
    const int g=lane>>2, c2=2*(lane&3);
    #pragma unroll
    for(int mt=0;mt<2;++mt)
        #pragma unroll
        for(int nt=0;nt<2;++nt){
            const int n0=wn*16+nt*8+c2;
            const float bv0=bias[n0], bv1=bias[n0+1];
            const float* d=D[mt*2+nt];
            uint32_t s[2];
            const uint32_t a0=outB+((wm*32+mt*16+g)*XS+n0)*2;
            split2pair(lrelu(d[0]+bv0), lrelu(d[1]+bv1), s);
            sts32(a0,s[0]); sts32(a0+XSPL,s[1]);
            const uint32_t a1=a0+8*XS*2;
            split2pair(lrelu(d[2]+bv0), lrelu(d[3]+bv1), s);
            sts32(a1,s[0]); sts32(a1+XSPL,s[1]);
        }
}

__global__ void __launch_bounds__(TPB,1)
reg1stage_emu(const float* __restrict__ x,
              const float* __restrict__ W1g, const float* __restrict__ b1g,
              const float* __restrict__ W2g, const float* __restrict__ b2g,
              const float* __restrict__ W3g, const float* __restrict__ b3g,
              const float* __restrict__ Wr,  const float* __restrict__ br,
              float* __restrict__ out)
{
    extern __shared__ char smem[];
    const uint32_t sb = smem_u32(smem);
    float* smf = reinterpret_cast<float*>(smem);
    float* sV1 = reinterpret_cast<float*>(smem+SM_PV1);
    float* sV2 = reinterpret_cast<float*>(smem+SM_PV2);
    int*   sI1 = reinterpret_cast<int*>(smem+SM_PI1);
    int*   sNF = reinterpret_cast<int*>(smem+SM_NF);
    int*   sFL = reinterpret_cast<int*>(smem+SM_FL);
    float* scr = reinterpret_cast<float*>(smem+SM_SCR);
    float* xf  = reinterpret_cast<float*>(smem+SM_XF);
    float* w1f = reinterpret_cast<float*>(smem+SM_WF1);
    float* w2f = reinterpret_cast<float*>(smem+SM_WF2);
    float* w3f = reinterpret_cast<float*>(smem+SM_WF3);
    const int tid=threadIdx.x, lane=tid&31, warp=tid>>5;
    const int wm=warp>>2, wn=warp&3;        // 4x4 warp grid
    const int h=blockIdx.x, b=blockIdx.y;

    // ---- stage weights: fp32 -> 2 bf16 splits (+ fp32 copies for recompute) ----
    {
        const float* g1=W1g+h*4096;
        const float* g2=W2g+h*4096;
        #pragma unroll
        for(int i=0;i<4;++i){
            const int p=tid+i*TPB;                 // pair 0..2047
            const int n=p>>5, c0=(p&31)*2;
            uint32_t s[2];
            const float2 v1=*reinterpret_cast<const float2*>(g1+n*64+c0);
            split2pair(v1.x,v1.y,s);
            uint32_t a=sb+SM_W1+(n*XS+c0)*2;
            sts32(a,s[0]); sts32(a+WSPL,s[1]);
            w1f[n*65+c0]=v1.x; w1f[n*65+c0+1]=v1.y;
            const float2 v2=*reinterpret_cast<const float2*>(g2+n*64+c0);
            split2pair(v2.x,v2.y,s);
            a=sb+SM_W2+(n*XS+c0)*2;
            sts32(a,s[0]); sts32(a+WSPL,s[1]);
            w2f[n*65+c0]=v2.x; w2f[n*65+c0+1]=v2.y;
        }
        const float* g3=W3g+h*2048;
        #pragma unroll
        for(int i=0;i<2;++i){
            const int p=tid+i*TPB;                 // pair 0..1023
            const int n=p>>5, c0=(p&31)*2;
            uint32_t s[2];
            const float2 v=*reinterpret_cast<const float2*>(g3+n*64+c0);
            split2pair(v.x,v.y,s);
            const uint32_t a=sb+SM_W3+(n*XS+c0)*2;
            sts32(a,s[0]); sts32(a+W3SPL,s[1]);
            w3f[n*65+c0]=v.x; w3f[n*65+c0+1]=v.y;
        }
        // Wr [(h*K+k)][c][2] -> row n=2k+o, col c; 2 splits
        const float* gr=Wr+(size_t)(h*K)*128;
        const int n=tid>>3, k=n>>1, o=n&1;
        #pragma unroll
        for(int j=0;j<4;++j){
            const int c=2*((tid&7)+j*8);
            const float va=gr[k*128+c*2+o];
            const float vb=gr[k*128+(c+1)*2+o];
            uint32_t s[2];
            split2pair(va,vb,s);
            const uint32_t a=sb+SM_WR+(n*XS+c)*2;
            sts32(a,s[0]); sts32(a+WSPL,s[1]);
        }
        if(tid<64){
            smf[SM_B1/4+tid]=b1g[h*64+tid];
            smf[SM_B2/4+tid]=b2g[h*64+tid];
            smf[SM_BR/4+tid]=br[h*64+tid];
        }
        if(tid<32) smf[SM_B3/4+tid]=b3g[h*32+tid];
    }

    const size_t HW=(size_t)H*Wd;
    const float* xbase=x+(size_t)b*64*HW+(size_t)h*Wd;
    const int pix_base=(b*H+h)*Wd;
    const int plane=Bn*H*Wd;
    const float inv_k=1.0f/(float)K;

    // lane-resolved ldmatrix bases
    const uint32_t aRel=((wm*32+(lane&15))*XS+(lane>>4)*8)*2;
    const uint32_t bRel=(((lane>>4)*8+(lane&7))*XS+((lane>>3)&1)*8)*2;
    const uint32_t aX =sb+SM_X +aRel;
    const uint32_t aY0=sb+SM_Y0+aRel;
    const uint32_t bW1=sb+SM_W1+bRel+(wn*16)*XS*2;
    const uint32_t bW2=sb+SM_W2+bRel+(wn*16)*XS*2;
    const uint32_t bW3=sb+SM_W3+bRel+(wn*16)*XS*2;   // valid for wn<2
    const uint32_t bWR=sb+SM_WR+bRel+(wn*16)*XS*2;

    __syncthreads();

    for(int wt=0;wt<WT;++wt){
        const int w0=wt*PXT;

        // ---- stage X: fp32 copy + 2 bf16 splits ----
        {
            if(tid==0) *sNF=0;
            const int px=tid&127, c0=(tid>>7)*16;
            const int wcl=min(w0+px, Wd-1);
            const float* xp=xbase+wcl;
            #pragma unroll
            for(int j=0;j<8;++j){
                const int c=c0+2*j;
                const float va=__ldg(xp+(size_t)c*HW);
                const float vb=__ldg(xp+(size_t)(c+1)*HW);
                xf[px*65+c]=va; xf[px*65+c+1]=vb;
                uint32_t s[2];
                split2pair(va,vb,s);
                const uint32_t a=sb+SM_X+(px*XS+c)*2;
                sts32(a,s[0]); sts32(a+XSPL,s[1]);
            }
        }
        __syncthreads();

        // ---- L1: Y0 = lrelu(X.W1^T+b1) ----
        {
            float D1[4][4];
            gemm3(aX,bW1,WSPL,D1);
            epi2(D1, smf+SM_B1/4, sb+SM_Y0, wm, wn, lane);
        }
        // ---- Dr = X.Wr^T, kept in regs across L2 ----
        float Dr[4][4];
        gemm3(aX,bWR,WSPL,Dr);
        __syncthreads();            // Y0 published; X-split reads done

        // ---- L2: Y1 = lrelu(Y0.W2^T+b2) -> overlays X splits ----
        {
            float D2[4][4];
            gemm3(aY0,bW2,WSPL,D2);
            epi2(D2, smf+SM_B2/4, sb+SM_X, wm, wn, lane);
        }
        __syncthreads();            // Y1 published; Y0 reads done

        // ---- L3 (warps wn<2): cls logits -> per-pixel top-2 partials ----
        if(wn<2){
            float D3[4][4];
            gemm3(aX,bW3,W3SPL,D3);
            const float* b3s=smf+SM_B3/4;
            const int g=lane>>2, c2=2*(lane&3);
            #pragma unroll
            for(int mt=0;mt<2;++mt){
                #pragma unroll
                for(int half=0;half<2;++half){
                    float v1=-3.402823466e38f, v2=-3.402823466e38f; int i1=0;
                    #pragma unroll
                    for(int nt=0;nt<2;++nt){
                        const int base=wn*16+nt*8+c2;
                        #pragma unroll
                        for(int q=0;q<2;++q){
                            const float v=D3[mt*2+nt][half*2+q]+b3s[base+q];
                            if(v>v1){ v2=v1; v1=v; i1=base+q; }
                            else if(v>v2){ v2=v; }
                        }
                    }
                    #pragma unroll
                    for(int m=1;m<=2;m<<=1){
                        const float u1=__shfl_xor_sync(0xFFFFFFFFu,v1,m);
                        const int   j1=__shfl_xor_sync(0xFFFFFFFFu,i1,m);
                        const float u2=__shfl_xor_sync(0xFFFFFFFFu,v2,m);
                        if(u1>v1 || (u1==v1 && j1<i1)){ v2=fmaxf(v1,u2); v1=u1; i1=j1; }
                        else { v2=fmaxf(u1,v2); }
                    }
                    if((lane&3)==0){
                        const int r=wm*32+mt*16+half*8+g;
                        sV1[wn*128+r]=v1; sV2[wn*128+r]=v2; sI1[wn*128+r]=i1;
                    }
                }
            }
        }
        // ---- spill Dr (f32) into freed Y0 region (all warps) ----
        {
            float* dr=reinterpret_cast<float*>(smem+SM_DR);
            const int g=lane>>2, c2=2*(lane&3);
            #pragma unroll
            for(int mt=0;mt<2;++mt)
                #pragma unroll
                for(int nt=0;nt<2;++nt){
                    const int n0=wn*16+nt*8+c2;
                    const float* d=Dr[mt*2+nt];
                    *reinterpret_cast<float2*>(dr+(wm*32+mt*16+g)*DRS+n0)  =make_float2(d[0],d[1]);
                    *reinterpret_cast<float2*>(dr+(wm*32+mt*16+g+8)*DRS+n0)=make_float2(d[2],d[3]);
                }
        }
        __syncthreads();

        // ---- tail A: merge top-2, flag near-ties, write clear winners ----
        if(tid<128){
            const int px=tid, wc=w0+px;
            if(wc<Wd){
                const float v1a=sV1[px],     v2a=sV2[px];     const int i1a=sI1[px];
                const float v1b=sV1[128+px], v2b=sV2[128+px]; const int i1b=sI1[128+px];
                float top1, sec; int bk;
                if(v1b>v1a){ top1=v1b; bk=i1b; sec=fmaxf(v1a,v2b); }
                else       { top1=v1a; bk=i1a; sec=fmaxf(v1b,v2a); }  // tie -> lower ✓
                if(top1-sec < TAU){
                    const int f=atomicAdd(sNF,1);
                    sFL[f]=px;
                } else {
                    const float* dr=reinterpret_cast<const float*>(smem+SM_DR);
                    const float2 dv=*reinterpret_cast<const float2*>(dr+px*DRS+2*bk);
                    const float reg0=lrelu(dv.x+smf[SM_BR/4+2*bk]);
                    const float reg1=lrelu(dv.y+smf[SM_BR/4+2*bk+1]);
                    const int flat=h*K+bk;
                    out[pix_base+wc]      =((float)flat+reg0)*inv_k;
                    out[plane+pix_base+wc]=lrelu(reg1);
                }
            }
        }
        __syncthreads();

        // ---- tail B: exact fp32 recompute (smem weights) for flagged pixels ----
        {
            const int nF=*sNF;
            for(int f=warp; f<nF; f+=16){
                const int px=sFL[f];
                const float* xp=xf+px*65;
                float* y0=scr+warp*128;
                float* y1=y0+64;
                // L1: 2 outputs per lane, fully unrolled LDS+FMA
                #pragma unroll
                for(int r=0;r<2;++r){
                    const int o=lane+r*32;
                    float acc=smf[SM_B1/4+o];
                    const float* wr=w1f+o*65;
                    #pragma unroll
                    for(int c=0;c<64;++c) acc=fmaf(wr[c],xp[c],acc);
                    y0[o]=lrelu(acc);
                }
                __syncwarp();
                // L2
                #pragma unroll
                for(int r=0;r<2;++r){
                    const int o=lane+r*32;
                    float acc=smf[SM_B2/4+o];
                    const float* wr=w2f+o*65;
                    #pragma unroll
                    for(int c=0;c<64;++c) acc=fmaf(wr[c],y0[c],acc);
                    y1[o]=lrelu(acc);
                }
                __syncwarp();
                // L3 + warp argmax (first-max)
                float v; int idx=lane;
                {
                    float acc=smf[SM_B3/4+lane];
                    const float* wr=w3f+lane*65;
                    #pragma unroll
                    for(int c=0;c<64;++c) acc=fmaf(wr[c],y1[c],acc);
                    v=acc;
                }
                #pragma unroll
                for(int m=16;m>=1;m>>=1){
                    const float ov=__shfl_xor_sync(0xFFFFFFFFu,v,m);
                    const int   oi=__shfl_xor_sync(0xFFFFFFFFu,idx,m);
                    if(ov>v || (ov==v && oi<idx)){ v=ov; idx=oi; }
                }
                if(lane==0){
                    const int bk=idx, wc=w0+px;
                    const float* dr=reinterpret_cast<const float*>(smem+SM_DR);
                    const float2 dv=*reinterpret_cast<const float2*>(dr+px*DRS+2*bk);
                    const float reg0=lrelu(dv.x+smf[SM_BR/4+2*bk]);
                    const float reg1=lrelu(dv.y+smf[SM_BR/4+2*bk+1]);
                    const int flat=h*K+bk;
                    out[pix_base+wc]      =((float)flat+reg0)*inv_k;
                    out[plane+pix_base+wc]=lrelu(reg1);
                }
            }
        }
        __syncthreads();            // dr/xf/flags reads done before next tile
    }
}

extern "C" void kernel_launch(void* const* d_in, const int* in_sizes, int n_in,
                              void* d_out, int out_size)
{
    const float* x =(const float*)d_in[0];
    const float* W1=(const float*)d_in[1];
    const float* b1=(const float*)d_in[2];
    const float* W2=(const float*)d_in[3];
    const float* b2=(const float*)d_in[4];
    const float* W3=(const float*)d_in[5];
    const float* b3=(const float*)d_in[6];
    const float* Wr=(const float*)d_in[7];
    const float* br=(const float*)d_in[8];
    float* out=(float*)d_out;

    cudaFuncSetAttribute(reg1stage_emu,
                         cudaFuncAttributeMaxDynamicSharedMemorySize, SMEM_BYTES);
    dim3 grid(H,Bn);
    reg1stage_emu<<<grid,TPB,SMEM_BYTES>>>(x,W1,b1,W2,b2,W3,b3,Wr,br,out);
}

// round 13
// speedup vs baseline: 5.2962x; 1.0917x over previous
#include <cuda_runtime.h>
#include <cuda_bf16.h>
#include <cstdint>

namespace {
constexpr int H=448, Wd=608, K=32, Bn=2, TPB=512, PXT=128, WT=5;
constexpr int XS=72;                        // bf16 row stride (144B = 9*16B)
constexpr int XSPL=128*XS*2;                // 18432 per activation split
constexpr int WSPL=64*XS*2;                 // 9216 per 64-row weight split
constexpr int W3SPL=32*XS*2;                // 4608
constexpr float TAU=2e-4f;                  // near-tie gap threshold (abs)

constexpr int SM_B1=0, SM_B2=256, SM_B3=512, SM_BR=640;
constexpr int SM_PV1=1024;                  // [4][128] f32 top1 val (2048)
constexpr int SM_PV2=3072;                  // [4][128] f32 top2 val (2048)
constexpr int SM_PI1=5120;                  // [4][128] i32 top1 idx (2048)
constexpr int SM_NF=7168;                   // flag count
constexpr int SM_FL=7296;                   // flag list [128]
constexpr int SM_SCR=7808;                  // 16 warps x 128 f32 scratch (8192)
constexpr int SM_XF=16000;                  // x fp32 [128][65] (33280)
constexpr int SM_X =49280;                  // X splits x2 (Y1 overlays after Dr)
constexpr int SM_Y0=SM_X+2*XSPL;            // 86144 (Dr f32 overlay after L2)
constexpr int SM_W1=SM_Y0+2*XSPL;           // 123008
constexpr int SM_W2=SM_W1+2*WSPL;           // 141440
constexpr int SM_W3=SM_W2+2*WSPL;           // 159872
constexpr int SM_WR=SM_W3+2*W3SPL;          // 169088
constexpr int SM_WF1=SM_WR+2*WSPL;          // 187520  fp32 W1 [64][65]
constexpr int SM_WF2=SM_WF1+64*65*4;        // 204160  fp32 W2 [64][65]
constexpr int SM_WF3=SM_WF2+64*65*4;        // 220800  fp32 W3 [32][65]
constexpr int SMEM_BYTES=SM_WF3+32*65*4;    // 229120 (< 232448 cap)
constexpr int SM_DR=SM_Y0;
constexpr int DRS=66;
}

__device__ __forceinline__ float lrelu(float v){ return v>=0.f ? v : 0.01f*v; }
__device__ __forceinline__ uint32_t smem_u32(const void* p){
    uint32_t a;
    asm("{ .reg .u64 t; cvta.to.shared.u64 t, %1; cvt.u32.u64 %0, t; }" : "=r"(a) : "l"(p));
    return a;
}
__device__ __forceinline__ void sts32(uint32_t a, uint32_t v){
    asm volatile("st.shared.b32 [%0], %1;" :: "r"(a), "r"(v) : "memory");
}
__device__ __forceinline__ void ldsm4(uint32_t addr, uint32_t* r){
    asm volatile("ldmatrix.sync.aligned.m8n8.x4.shared.b16 {%0,%1,%2,%3}, [%4];"
                 : "=r"(r[0]), "=r"(r[1]), "=r"(r[2]), "=r"(r[3]) : "r"(addr));
}
__device__ __forceinline__ void ldsm2(uint32_t addr, uint32_t* r){
    asm volatile("ldmatrix.sync.aligned.m8n8.x2.shared.b16 {%0,%1}, [%2];"
                 : "=r"(r[0]), "=r"(r[1]) : "r"(addr));
}
__device__ __forceinline__ void mma_bf16(float d[4], const uint32_t a[4], uint32_t b0, uint32_t b1){
    asm volatile("mma.sync.aligned.m16n8k16.row.col.f32.bf16.bf16.f32 "
                 "{%0,%1,%2,%3},{%4,%5,%6,%7},{%8,%9},{%0,%1,%2,%3};"
                 : "+f"(d[0]), "+f"(d[1]), "+f"(d[2]), "+f"(d[3])
                 : "r"(a[0]), "r"(a[1]), "r"(a[2]), "r"(a[3]), "r"(b0), "r"(b1));
}
__device__ __forceinline__ uint32_t prmt_(uint32_t a, uint32_t b, uint32_t s){
    uint32_t d; asm("prmt.b32 %0,%1,%2,%3;" : "=r"(d) : "r"(a), "r"(b), "r"(s)); return d;
}
// 2-way split (round-to-nearest-class): s0 = round(v) hi-bf16 via +0x8000 carry,
// residual r = v - s0 is EXACT in fp32; s1 = rn(r). |r| <= 2^-9|v| as with rn.
__device__ __forceinline__ void split2pair(float a, float b, uint32_t s[2]){
    const uint32_t ia=__float_as_uint(a)+0x8000u, ib=__float_as_uint(b)+0x8000u;
    s[0]=prmt_(ia, ib, 0x7632u);                       // [hb(b)|hb(a)]
    const float ra=a-__uint_as_float(ia&0xFFFF0000u);
    const float rb=b-__uint_as_float(ib&0xFFFF0000u);
    uint32_t r; asm("cvt.rn.bf16x2.f32 %0, %1, %2;" : "=r"(r) : "f"(rb), "f"(ra));
    s[1]=r;
}

// ---- 2-split 3-pass emulated GEMMs; warp tile 32px x 16n ----
// single (L2): all B fragments hoisted (deep LDSM MLP), ks fully unrolled
__device__ __forceinline__ void gemm3(uint32_t aB, uint32_t bB, float D[4][4]){
    uint32_t bf[4][2][4];
    #pragma unroll
    for(int ks=0;ks<4;++ks)
        #pragma unroll
        for(int s=0;s<2;++s) ldsm4(bB+s*WSPL+ks*32, bf[ks][s]);
    #pragma unroll
    for(int i=0;i<4;++i){ D[i][0]=D[i][1]=D[i][2]=D[i][3]=0.f; }
    constexpr int PA[3]={0,0,1}, PB[3]={0,1,0};
    #pragma unroll
    for(int ks=0;ks<4;++ks){
        uint32_t a[2][2][4];
        #pragma unroll
        for(int s=0;s<2;++s){
            ldsm4(aB+s*XSPL+ks*32, a[s][0]);
            ldsm4(aB+s*XSPL+16*XS*2+ks*32, a[s][1]);
        }
        #pragma unroll
        for(int p=0;p<3;++p)
            #pragma unroll
            for(int mt=0;mt<2;++mt)
                #pragma unroll
                for(int nt=0;nt<2;++nt)
                    mma_bf16(D[mt*2+nt], a[PA[p]][mt],
                             bf[ks][PB[p]][nt*2], bf[ks][PB[p]][nt*2+1]);
    }
}
// dual (L1 + Dr share A-fragments of X)
__device__ __forceinline__ void gemm3_dual(uint32_t aB, uint32_t b1B, uint32_t b2B,
                                           float D1[4][4], float D2[4][4]){
    #pragma unroll
    for(int i=0;i<4;++i){ D1[i][0]=D1[i][1]=D1[i][2]=D1[i][3]=0.f;
                          D2[i][0]=D2[i][1]=D2[i][2]=D2[i][3]=0.f; }
    constexpr int PA[3]={0,0,1}, PB[3]={0,1,0};
    #pragma unroll
    for(int ks=0;ks<4;++ks){
        uint32_t a[2][2][4];
        #pragma unroll
        for(int s=0;s<2;++s){
            ldsm4(aB+s*XSPL+ks*32, a[s][0]);
            ldsm4(aB+s*XSPL+16*XS*2+ks*32, a[s][1]);
        }
        uint32_t bf1[2][4], bf2[2][4];
        #pragma unroll
        for(int s=0;s<2;++s){
            ldsm4(b1B+s*WSPL+ks*32, bf1[s]);
            ldsm4(b2B+s*WSPL+ks*32, bf2[s]);
        }
        #pragma unroll
        for(int p=0;p<3;++p)
            #pragma unroll
            for(int mt=0;mt<2;++mt)
                #pragma unroll
                for(int nt=0;nt<2;++nt){
                    mma_bf16(D1[mt*2+nt], a[PA[p]][mt], bf1[PB[p]][nt*2], bf1[PB[p]][nt*2+1]);
                    mma_bf16(D2[mt*2+nt], a[PA[p]][mt], bf2[PB[p]][nt*2], bf2[PB[p]][nt*2+1]);
                }
    }
}
// narrow (L3): warp tile 32px x 8n, all 16 warps
__device__ __forceinline__ void gemm3_n8(uint32_t aB, uint32_t bB, float D[2][4]){
    uint32_t bf[4][2][2];
    #pragma unroll
    for(int ks=0;ks<4;++ks)
        #pragma unroll
        for(int s=0;s<2;++s) ldsm2(bB+s*W3SPL+ks*32, bf[ks][s]);
    #pragma unroll
    for(int i=0;i<2;++i){ D[i][0]=D[i][1]=D[i][2]=D[i][3]=0.f; }
    constexpr int PA[3]={0,0,1}, PB[3]={0,1,0};
    #pragma unroll
    for(int ks=0;ks<4;++ks){
        uint32_t a[2][2][4];
        #pragma unroll
        for(int s=0;s<2;++s){
            ldsm4(aB+s*XSPL+ks*32, a[s][0]);
            ldsm4(aB+s*XSPL+16*XS*2+ks*32, a[s][1]);
        }
        #pragma unroll
        for(int p=0;p<3;++p)
            #pragma unroll
            for(int mt=0;mt<2;++mt)
                mma_bf16(D[mt], a[PA[p]][mt], bf[ks][PB[p]][0], bf[ks][PB[p]][1]);
    }
}

// bias + lrelu + 2-split bf16 store; warp covers 32px x 16n
__device__ __forceinline__ void epi2(float D[4][4], const float* __restrict__ bias,
                                     uint32_t outB, int wm, int wn, int lane){
    const int g=lane>>2, c2=2*(lane&3);
    #pragma unroll
    for(int mt=0;mt<2;++mt)
        #pragma unroll
        for(int nt=0;nt<2;++nt){
            const int n0=wn*16+nt*8+c2;
            const float bv0=bias[n0], bv1=bias[n0+1];
            const float* d=D[mt*2+nt];
            uint32_t s[2];
            const uint32_t a0=outB+((wm*32+mt*16+g)*XS+n0)*2;
            split2pair(lrelu(d[0]+bv0), lrelu(d[1]+bv1), s);
            sts32(a0,s[0]); sts32(a0+XSPL,s[1]);
            const uint32_t a1=a0+8*XS*2;
            split2pair(lrelu(d[2]+bv0), lrelu(d[3]+bv1), s);
            sts32(a1,s[0]); sts32(a1+XSPL,s[1]);
        }
}

__global__ void __launch_bounds__(TPB,1)
reg1stage_emu(const float* __restrict__ x,
              const float* __restrict__ W1g, const float* __restrict__ b1g,
              const float* __restrict__ W2g, const float* __restrict__ b2g,
              const float* __restrict__ W3g, const float* __restrict__ b3g,
              const float* __restrict__ Wr,  const float* __restrict__ br,
              float* __restrict__ out)
{
    extern __shared__ char smem[];
    const uint32_t sb = smem_u32(smem);
    float* smf = reinterpret_cast<float*>(smem);
    float* sV1 = reinterpret_cast<float*>(smem+SM_PV1);
    float* sV2 = reinterpret_cast<float*>(smem+SM_PV2);
    int*   sI1 = reinterpret_cast<int*>(smem+SM_PI1);
    int*   sNF = reinterpret_cast<int*>(smem+SM_NF);
    int*   sFL = reinterpret_cast<int*>(smem+SM_FL);
    float* scr = reinterpret_cast<float*>(smem+SM_SCR);
    float* xf  = reinterpret_cast<float*>(smem+SM_XF);
    float* w1f = reinterpret_cast<float*>(smem+SM_WF1);
    float* w2f = reinterpret_cast<float*>(smem+SM_WF2);
    float* w3f = reinterpret_cast<float*>(smem+SM_WF3);
    const int tid=threadIdx.x, lane=tid&31, warp=tid>>5;
    const int wm=warp>>2, wn=warp&3;        // 4x4 warp grid
    const int h=blockIdx.x, b=blockIdx.y;

    // ---- stage weights: fp32 -> 2 bf16 splits (+ fp32 copies for recompute) ----
    {
        const float* g1=W1g+h*4096;
        const float* g2=W2g+h*4096;
        #pragma unroll
        for(int i=0;i<4;++i){
            const int p=tid+i*TPB;                 // pair 0..2047
            const int n=p>>5, c0=(p&31)*2;
            uint32_t s[2];
            const float2 v1=*reinterpret_cast<const float2*>(g1+n*64+c0);
            split2pair(v1.x,v1.y,s);
            uint32_t a=sb+SM_W1+(n*XS+c0)*2;
            sts32(a,s[0]); sts32(a+WSPL,s[1]);
            w1f[n*65+c0]=v1.x; w1f[n*65+c0+1]=v1.y;
            const float2 v2=*reinterpret_cast<const float2*>(g2+n*64+c0);
            split2pair(v2.x,v2.y,s);
            a=sb+SM_W2+(n*XS+c0)*2;
            sts32(a,s[0]); sts32(a+WSPL,s[1]);
            w2f[n*65+c0]=v2.x; w2f[n*65+c0+1]=v2.y;
        }
        const float* g3=W3g+h*2048;
        #pragma unroll
        for(int i=0;i<2;++i){
            const int p=tid+i*TPB;                 // pair 0..1023
            const int n=p>>5, c0=(p&31)*2;
            uint32_t s[2];
            const float2 v=*reinterpret_cast<const float2*>(g3+n*64+c0);
            split2pair(v.x,v.y,s);
            const uint32_t a=sb+SM_W3+(n*XS+c0)*2;
            sts32(a,s[0]); sts32(a+W3SPL,s[1]);
            w3f[n*65+c0]=v.x; w3f[n*65+c0+1]=v.y;
        }
        // Wr [(h*K+k)][c][2] -> row n=2k+o, col c; 2 splits
        const float* gr=Wr+(size_t)(h*K)*128;
        const int n=tid>>3, k=n>>1, o=n&1;
        #pragma unroll
        for(int j=0;j<4;++j){
            const int c=2*((tid&7)+j*8);
            const float va=gr[k*128+c*2+o];
            const float vb=gr[k*128+(c+1)*2+o];
            uint32_t s[2];
            split2pair(va,vb,s);
            const uint32_t a=sb+SM_WR+(n*XS+c)*2;
            sts32(a,s[0]); sts32(a+WSPL,s[1]);
        }
        if(tid<64){
            smf[SM_B1/4+tid]=b1g[h*64+tid];
            smf[SM_B2/4+tid]=b2g[h*64+tid];
            smf[SM_BR/4+tid]=br[h*64+tid];
        }
        if(tid<32) smf[SM_B3/4+tid]=b3g[h*32+tid];
    }

    const size_t HW=(size_t)H*Wd;
    const float* xbase=x+(size_t)b*64*HW+(size_t)h*Wd;
    const int pix_base=(b*H+h)*Wd;
    const int plane=Bn*H*Wd;
    const float inv_k=1.0f/(float)K;

    // lane-resolved ldmatrix bases
    const uint32_t aRel=((wm*32+(lane&15))*XS+(lane>>4)*8)*2;
    const uint32_t bRel=(((lane>>4)*8+(lane&7))*XS+((lane>>3)&1)*8)*2;
    const uint32_t aX =sb+SM_X +aRel;
    const uint32_t aY0=sb+SM_Y0+aRel;
    const uint32_t bW1=sb+SM_W1+bRel+(wn*16)*XS*2;
    const uint32_t bW2=sb+SM_W2+bRel+(wn*16)*XS*2;
    const uint32_t bW3=sb+SM_W3+bRel+(wn*8)*XS*2;    // all 16 warps, 8 classes each
    const uint32_t bWR=sb+SM_WR+bRel+(wn*16)*XS*2;

    __syncthreads();

    for(int wt=0;wt<WT;++wt){
        const int w0=wt*PXT;

        // ---- stage X: fp32 copy + 2 bf16 splits ----
        {
            if(tid==0) *sNF=0;
            const int px=tid&127, c0=(tid>>7)*16;
            const int wcl=min(w0+px, Wd-1);
            const float* xp=xbase+wcl;
            #pragma unroll
            for(int j=0;j<8;++j){
                const int c=c0+2*j;
                const float va=__ldg(xp+(size_t)c*HW);
                const float vb=__ldg(xp+(size_t)(c+1)*HW);
                xf[px*65+c]=va; xf[px*65+c+1]=vb;
                uint32_t s[2];
                split2pair(va,vb,s);
                const uint32_t a=sb+SM_X+(px*XS+c)*2;
                sts32(a,s[0]); sts32(a+XSPL,s[1]);
            }
        }
        __syncthreads();

        // ---- L1 + Dr fused (share A): Y0 = lrelu(X.W1^T+b1); Dr = X.Wr^T ----
        float Dr[4][4];
        {
            float D1[4][4];
            gemm3_dual(aX, bW1, bWR, D1, Dr);
            epi2(D1, smf+SM_B1/4, sb+SM_Y0, wm, wn, lane);
        }
        __syncthreads();            // Y0 published; X-split reads done

        // ---- L2: Y1 = lrelu(Y0.W2^T+b2) -> overlays X splits ----
        {
            float D2[4][4];
            gemm3(aY0, bW2, D2);
            epi2(D2, smf+SM_B2/4, sb+SM_X, wm, wn, lane);
        }
        __syncthreads();            // Y1 published; Y0 reads done

        // ---- L3 (ALL warps, 8 classes each): top-2 partials ----
        {
            float D3[2][4];
            gemm3_n8(aX, bW3, D3);
            const float* b3s=smf+SM_B3/4;
            const int g=lane>>2, c2=2*(lane&3);
            const int n0=wn*8+c2;
            const float bv0=b3s[n0], bv1=b3s[n0+1];
            #pragma unroll
            for(int mt=0;mt<2;++mt){
                #pragma unroll
                for(int half=0;half<2;++half){
                    const float va=D3[mt][half*2]+bv0;
                    const float vb=D3[mt][half*2+1]+bv1;
                    float v1 = (vb>va)? vb : va;
                    int   i1 = (vb>va)? n0+1 : n0;   // tie -> lower class ✓
                    float v2 = (vb>va)? va : vb;
                    #pragma unroll
                    for(int m=1;m<=2;m<<=1){
                        const float u1=__shfl_xor_sync(0xFFFFFFFFu,v1,m);
                        const int   j1=__shfl_xor_sync(0xFFFFFFFFu,i1,m);
                        const float u2=__shfl_xor_sync(0xFFFFFFFFu,v2,m);
                        if(u1>v1 || (u1==v1 && j1<i1)){ v2=fmaxf(v1,u2); v1=u1; i1=j1; }
                        else { v2=fmaxf(u1,v2); }
                    }
                    if((lane&3)==0){
                        const int r=wm*32+mt*16+half*8+g;
                        sV1[wn*128+r]=v1; sV2[wn*128+r]=v2; sI1[wn*128+r]=i1;
                    }
                }
            }
        }
        // ---- spill Dr (f32) into freed Y0 region (all warps) ----
        {
            float* dr=reinterpret_cast<float*>(smem+SM_DR);
            const int g=lane>>2, c2=2*(lane&3);
            #pragma unroll
            for(int mt=0;mt<2;++mt)
                #pragma unroll
                for(int nt=0;nt<2;++nt){
                    const int n0=wn*16+nt*8+c2;
                    const float* d=Dr[mt*2+nt];
                    *reinterpret_cast<float2*>(dr+(wm*32+mt*16+g)*DRS+n0)  =make_float2(d[0],d[1]);
                    *reinterpret_cast<float2*>(dr+(wm*32+mt*16+g+8)*DRS+n0)=make_float2(d[2],d[3]);
                }
        }
        __syncthreads();

        // ---- tail A: merge 4 top-2 partials, flag near-ties, write winners ----
        if(tid<128){
            const int px=tid, wc=w0+px;
            if(wc<Wd){
                float top1=-3.402823466e38f, sec=-3.402823466e38f; int bk=0;
                #pragma unroll
                for(int q=0;q<4;++q){                 // ascending class groups
                    const float v1=sV1[q*128+px], v2=sV2[q*128+px];
                    const int   i1=sI1[q*128+px];
                    if(v1>top1){ sec=fmaxf(top1,v2); top1=v1; bk=i1; }
                    else       { sec=fmaxf(sec,v1); }
                }
                if(top1-sec < TAU){
                    const int f=atomicAdd(sNF,1);
                    sFL[f]=px;
                } else {
                    const float* dr=reinterpret_cast<const float*>(smem+SM_DR);
                    const float2 dv=*reinterpret_cast<const float2*>(dr+px*DRS+2*bk);
                    const float reg0=lrelu(dv.x+smf[SM_BR/4+2*bk]);
                    const float reg1=lrelu(dv.y+smf[SM_BR/4+2*bk+1]);
                    const int flat=h*K+bk;
                    out[pix_base+wc]      =((float)flat+reg0)*inv_k;
                    out[plane+pix_base+wc]=lrelu(reg1);
                }
            }
        }
        __syncthreads();

        // ---- tail B: exact fp32 recompute (smem weights) for flagged pixels ----
        {
            const int nF=*sNF;
            for(int f=warp; f<nF; f+=16){
                const int px=sFL[f];
                const float* xp=xf+px*65;
                float* y0=scr+warp*128;
                float* y1=y0+64;
                #pragma unroll
                for(int r=0;r<2;++r){
                    const int o=lane+r*32;
                    float acc=smf[SM_B1/4+o];
                    const float* wr=w1f+o*65;
                    #pragma unroll
                    for(int c=0;c<64;++c) acc=fmaf(wr[c],xp[c],acc);
                    y0[o]=lrelu(acc);
                }
                __syncwarp();
                #pragma unroll
                for(int r=0;r<2;++r){
                    const int o=lane+r*32;
                    float acc=smf[SM_B2/4+o];
                    const float* wr=w2f+o*65;
                    #pragma unroll
                    for(int c=0;c<64;++c) acc=fmaf(wr[c],y0[c],acc);
                    y1[o]=lrelu(acc);
                }
                __syncwarp();
                float v; int idx=lane;
                {
                    float acc=smf[SM_B3/4+lane];
                    const float* wr=w3f+lane*65;
                    #pragma unroll
                    for(int c=0;c<64;++c) acc=fmaf(wr[c],y1[c],acc);
                    v=acc;
                }
                #pragma unroll
                for(int m=16;m>=1;m>>=1){
                    const float ov=__shfl_xor_sync(0xFFFFFFFFu,v,m);
                    const int   oi=__shfl_xor_sync(0xFFFFFFFFu,idx,m);
                    if(ov>v || (ov==v && oi<idx)){ v=ov; idx=oi; }
                }
                if(lane==0){
                    const int bk=idx, wc=w0+px;
                    const float* dr=reinterpret_cast<const float*>(smem+SM_DR);
                    const float2 dv=*reinterpret_cast<const float2*>(dr+px*DRS+2*bk);
                    const float reg0=lrelu(dv.x+smf[SM_BR/4+2*bk]);
                    const float reg1=lrelu(dv.y+smf[SM_BR/4+2*bk+1]);
                    const int flat=h*K+bk;
                    out[pix_base+wc]      =((float)flat+reg0)*inv_k;
                    out[plane+pix_base+wc]=lrelu(reg1);
                }
            }
        }
        __syncthreads();            // dr/xf/flags reads done before next tile
    }
}

extern "C" void kernel_launch(void* const* d_in, const int* in_sizes, int n_in,
                              void* d_out, int out_size)
{
    const float* x =(const float*)d_in[0];
    const float* W1=(const float*)d_in[1];
    const float* b1=(const float*)d_in[2];
    const float* W2=(const float*)d_in[3];
    const float* b2=(const float*)d_in[4];
    const float* W3=(const float*)d_in[5];
    const float* b3=(const float*)d_in[6];
    const float* Wr=(const float*)d_in[7];
    const float* br=(const float*)d_in[8];
    float* out=(float*)d_out;

    cudaFuncSetAttribute(reg1stage_emu,
                         cudaFuncAttributeMaxDynamicSharedMemorySize, SMEM_BYTES);
    dim3 grid(H,Bn);
    reg1stage_emu<<<grid,TPB,SMEM_BYTES>>>(x,W1,b1,W2,b2,W3,b3,Wr,br,out);
}

// round 14
// speedup vs baseline: 5.5656x; 1.0509x over previous
#include <cuda_runtime.h>
#include <cuda_bf16.h>
#include <cstdint>

namespace {
constexpr int H=448, Wd=608, K=32, Bn=2, TPB=512, PXT=128;
constexpr int NSM=148;                      // persistent CTAs
constexpr int NTILES=H*Bn*5;                // 4480 (h,b,wt) tiles
constexpr int XS=72;                        // bf16 row stride (144B = 9*16B)
constexpr int XSPL=128*XS*2;                // 18432 per activation split
constexpr int WSPL=64*XS*2;                 // 9216 per 64-row weight split
constexpr int W3SPL=32*XS*2;                // 4608
constexpr float TAU=2e-4f;                  // near-tie gap threshold (abs)

constexpr int SM_B1=0, SM_B2=256, SM_B3=512, SM_BR=640;
constexpr int SM_PV1=1024;                  // [4][128] f32 top1 val
constexpr int SM_PV2=3072;                  // [4][128] f32 top2 val
constexpr int SM_PI1=5120;                  // [4][128] i32 top1 idx
constexpr int SM_NF=7168;
constexpr int SM_FL=7296;                   // flag list [128]
constexpr int SM_SCR=7808;                  // 16 warps x 128 f32 (8192)
constexpr int SM_XA=16000;                  // raw x prefetch [64][128] f32 (32768)
constexpr int SM_X =48768;                  // X splits x2 (Y1 overlays)
constexpr int SM_Y0=SM_X+2*XSPL;            // 85632 (Dr f32 overlay)
constexpr int SM_W1=SM_Y0+2*XSPL;           // 122496
constexpr int SM_W2=SM_W1+2*WSPL;           // 140928
constexpr int SM_W3=SM_W2+2*WSPL;           // 159360
constexpr int SM_WR=SM_W3+2*W3SPL;          // 168576
constexpr int SM_WF1=SM_WR+2*WSPL;          // 187008  fp32 W1 [64][65]
constexpr int SM_WF2=SM_WF1+64*65*4;        // 203648  fp32 W2 [64][65]
constexpr int SM_WF3=SM_WF2+64*65*4;        // 220288  fp32 W3 [32][65]
constexpr int SMEM_BYTES=SM_WF3+32*65*4;    // 228608 (< 232448 cap)
constexpr int SM_DR=SM_Y0;
constexpr int DRS=66;
}

__device__ __forceinline__ float lrelu(float v){ return v>=0.f ? v : 0.01f*v; }
__device__ __forceinline__ uint32_t smem_u32(const void* p){
    uint32_t a;
    asm("{ .reg .u64 t; cvta.to.shared.u64 t, %1; cvt.u32.u64 %0, t; }" : "=r"(a) : "l"(p));
    return a;
}
__device__ __forceinline__ void sts32(uint32_t a, uint32_t v){
    asm volatile("st.shared.b32 [%0], %1;" :: "r"(a), "r"(v) : "memory");
}
__device__ __forceinline__ void cp16(uint32_t dst, const void* src){
    asm volatile("cp.async.cg.shared.global [%0], [%1], 16;" :: "r"(dst), "l"(src) : "memory");
}
__device__ __forceinline__ void ldsm4(uint32_t addr, uint32_t* r){
    asm volatile("ldmatrix.sync.aligned.m8n8.x4.shared.b16 {%0,%1,%2,%3}, [%4];"
                 : "=r"(r[0]), "=r"(r[1]), "=r"(r[2]), "=r"(r[3]) : "r"(addr));
}
__device__ __forceinline__ void ldsm2(uint32_t addr, uint32_t* r){
    asm volatile("ldmatrix.sync.aligned.m8n8.x2.shared.b16 {%0,%1}, [%2];"
                 : "=r"(r[0]), "=r"(r[1]) : "r"(addr));
}
__device__ __forceinline__ void mma_bf16(float d[4], const uint32_t a[4], uint32_t b0, uint32_t b1){
    asm volatile("mma.sync.aligned.m16n8k16.row.col.f32.bf16.bf16.f32 "
                 "{%0,%1,%2,%3},{%4,%5,%6,%7},{%8,%9},{%0,%1,%2,%3};"
                 : "+f"(d[0]), "+f"(d[1]), "+f"(d[2]), "+f"(d[3])
                 : "r"(a[0]), "r"(a[1]), "r"(a[2]), "r"(a[3]), "r"(b0), "r"(b1));
}
__device__ __forceinline__ uint32_t prmt_(uint32_t a, uint32_t b, uint32_t s){
    uint32_t d; asm("prmt.b32 %0,%1,%2,%3;" : "=r"(d) : "r"(a), "r"(b), "r"(s)); return d;
}
// 2-way split: s0 = hi-bf16(v + 0x8000 carry); residual EXACT in fp32; s1 = rn(r).
__device__ __forceinline__ void split2pair(float a, float b, uint32_t s[2]){
    const uint32_t ia=__float_as_uint(a)+0x8000u, ib=__float_as_uint(b)+0x8000u;
    s[0]=prmt_(ia, ib, 0x7632u);
    const float ra=a-__uint_as_float(ia&0xFFFF0000u);
    const float rb=b-__uint_as_float(ib&0xFFFF0000u);
    uint32_t r; asm("cvt.rn.bf16x2.f32 %0, %1, %2;" : "=r"(r) : "f"(rb), "f"(ra));
    s[1]=r;
}

// ---- 2-split 3-pass emulated GEMMs; warp tile 32px x 16n ----
__device__ __forceinline__ void gemm3(uint32_t aB, uint32_t bB, float D[4][4]){
    uint32_t bf[4][2][4];
    #pragma unroll
    for(int ks=0;ks<4;++ks)
        #pragma unroll
        for(int s=0;s<2;++s) ldsm4(bB+s*WSPL+ks*32, bf[ks][s]);
    #pragma unroll
    for(int i=0;i<4;++i){ D[i][0]=D[i][1]=D[i][2]=D[i][3]=0.f; }
    constexpr int PA[3]={0,0,1}, PB[3]={0,1,0};
    #pragma unroll
    for(int ks=0;ks<4;++ks){
        uint32_t a[2][2][4];
        #pragma unroll
        for(int s=0;s<2;++s){
            ldsm4(aB+s*XSPL+ks*32, a[s][0]);
            ldsm4(aB+s*XSPL+16*XS*2+ks*32, a[s][1]);
        }
        #pragma unroll
        for(int p=0;p<3;++p)
            #pragma unroll
            for(int mt=0;mt<2;++mt)
                #pragma unroll
                for(int nt=0;nt<2;++nt)
                    mma_bf16(D[mt*2+nt], a[PA[p]][mt],
                             bf[ks][PB[p]][nt*2], bf[ks][PB[p]][nt*2+1]);
    }
}
__device__ __forceinline__ void gemm3_dual(uint32_t aB, uint32_t b1B, uint32_t b2B,
                                           float D1[4][4], float D2[4][4]){
    #pragma unroll
    for(int i=0;i<4;++i){ D1[i][0]=D1[i][1]=D1[i][2]=D1[i][3]=0.f;
                          D2[i][0]=D2[i][1]=D2[i][2]=D2[i][3]=0.f; }
    constexpr int PA[3]={0,0,1}, PB[3]={0,1,0};
    #pragma unroll
    for(int ks=0;ks<4;++ks){
        uint32_t a[2][2][4];
        #pragma unroll
        for(int s=0;s<2;++s){
            ldsm4(aB+s*XSPL+ks*32, a[s][0]);
            ldsm4(aB+s*XSPL+16*XS*2+ks*32, a[s][1]);
        }
        uint32_t bf1[2][4], bf2[2][4];
        #pragma unroll
        for(int s=0;s<2;++s){
            ldsm4(b1B+s*WSPL+ks*32, bf1[s]);
            ldsm4(b2B+s*WSPL+ks*32, bf2[s]);
        }
        #pragma unroll
        for(int p=0;p<3;++p)
            #pragma unroll
            for(int mt=0;mt<2;++mt)
                #pragma unroll
                for(int nt=0;nt<2;++nt){
                    mma_bf16(D1[mt*2+nt], a[PA[p]][mt], bf1[PB[p]][nt*2], bf1[PB[p]][nt*2+1]);
                    mma_bf16(D2[mt*2+nt], a[PA[p]][mt], bf2[PB[p]][nt*2], bf2[PB[p]][nt*2+1]);
                }
    }
}
__device__ __forceinline__ void gemm3_n8(uint32_t aB, uint32_t bB, float D[2][4]){
    uint32_t bf[4][2][2];
    #pragma unroll
    for(int ks=0;ks<4;++ks)
        #pragma unroll
        for(int s=0;s<2;++s) ldsm2(bB+s*W3SPL+ks*32, bf[ks][s]);
    #pragma unroll
    for(int i=0;i<2;++i){ D[i][0]=D[i][1]=D[i][2]=D[i][3]=0.f; }
    constexpr int PA[3]={0,0,1}, PB[3]={0,1,0};
    #pragma unroll
    for(int ks=0;ks<4;++ks){
        uint32_t a[2][2][4];
        #pragma unroll
        for(int s=0;s<2;++s){
            ldsm4(aB+s*XSPL+ks*32, a[s][0]);
            ldsm4(aB+s*XSPL+16*XS*2+ks*32, a[s][1]);
        }
        #pragma unroll
        for(int p=0;p<3;++p)
            #pragma unroll
            for(int mt=0;mt<2;++mt)
                mma_bf16(D[mt], a[PA[p]][mt], bf[ks][PB[p]][0], bf[ks][PB[p]][1]);
    }
}

__device__ __forceinline__ void epi2(float D[4][4], const float* __restrict__ bias,
                                     uint32_t outB, int wm, int wn, int lane){
    const int g=lane>>2, c2=2*(lane&3);
    #pragma unroll
    for(int mt=0;mt<2;++mt)
        #pragma unroll
        for(int nt=0;nt<2;++nt){
            const int n0=wn*16+nt*8+c2;
            const float bv0=bias[n0], bv1=bias[n0+1];
            const float* d=D[mt*2+nt];
            uint32_t s[2];
            const uint32_t a0=outB+((wm*32+mt*16+g)*XS+n0)*2;
            split2pair(lrelu(d[0]+bv0), lrelu(d[1]+bv1), s);
            sts32(a0,s[0]); sts32(a0+XSPL,s[1]);
            const uint32_t a1=a0+8*XS*2;
            split2pair(lrelu(d[2]+bv0), lrelu(d[3]+bv1), s);
            sts32(a1,s[0]); sts32(a1+XSPL,s[1]);
        }
}

__global__ void __launch_bounds__(TPB,1)
reg1stage_emu(const float* __restrict__ x,
              const float* __restrict__ W1g, const float* __restrict__ b1g,
              const float* __restrict__ W2g, const float* __restrict__ b2g,
              const float* __restrict__ W3g, const float* __restrict__ b3g,
              const float* __restrict__ Wr,  const float* __restrict__ br,
              float* __restrict__ out)
{
    extern __shared__ char smem[];
    const uint32_t sb = smem_u32(smem);
    float* smf = reinterpret_cast<float*>(smem);
    float* sV1 = reinterpret_cast<float*>(smem+SM_PV1);
    float* sV2 = reinterpret_cast<float*>(smem+SM_PV2);
    int*   sI1 = reinterpret_cast<int*>(smem+SM_PI1);
    int*   sNF = reinterpret_cast<int*>(smem+SM_NF);
    int*   sFL = reinterpret_cast<int*>(smem+SM_FL);
    float* scr = reinterpret_cast<float*>(smem+SM_SCR);
    float* xa  = reinterpret_cast<float*>(smem+SM_XA);
    float* w1f = reinterpret_cast<float*>(smem+SM_WF1);
    float* w2f = reinterpret_cast<float*>(smem+SM_WF2);
    float* w3f = reinterpret_cast<float*>(smem+SM_WF3);
    const int tid=threadIdx.x, lane=tid&31, warp=tid>>5;
    const int wm=warp>>2, wn=warp&3;

    const size_t HW=(size_t)H*Wd;
    const int plane=Bn*H*Wd;
    const float inv_k=1.0f/(float)K;

    // lane-resolved ldmatrix bases
    const uint32_t aRel=((wm*32+(lane&15))*XS+(lane>>4)*8)*2;
    const uint32_t bRel=(((lane>>4)*8+(lane&7))*XS+((lane>>3)&1)*8)*2;
    const uint32_t aX =sb+SM_X +aRel;
    const uint32_t aY0=sb+SM_Y0+aRel;
    const uint32_t bW1=sb+SM_W1+bRel+(wn*16)*XS*2;
    const uint32_t bW2=sb+SM_W2+bRel+(wn*16)*XS*2;
    const uint32_t bW3=sb+SM_W3+bRel+(wn*8)*XS*2;
    const uint32_t bWR=sb+SM_WR+bRel+(wn*16)*XS*2;

    // persistent: contiguous tile range, hb = 2h+b, tile = hb*5+wt
    const int cta=blockIdx.x;
    const int t0=(int)(((long long)cta*NTILES)/NSM);
    const int t1=(int)(((long long)(cta+1)*NTILES)/NSM);
    int cur_h=-1;

    // initial prefetch for tile t0
    {
        const int hb=t0/5, wt=t0-hb*5, h=hb>>1, b=hb&1;
        const float* base=x+(size_t)b*64*HW+(size_t)h*Wd;
        #pragma unroll
        for(int i=0;i<4;++i){
            const int chunk=tid+i*TPB, c=chunk>>5, g=chunk&31;
            const int w=min(wt*PXT+g*4, Wd-4);
            cp16(sb+SM_XA+(c*128+g*4)*4, base+(size_t)c*HW+w);
        }
        asm volatile("cp.async.commit_group;" ::: "memory");
    }

    for(int t=t0;t<t1;++t){
        const int hb=t/5, wt=t-hb*5;
        const int h=hb>>1, b=hb&1;
        const int w0=wt*PXT;
        const int pix_base=(b*H+h)*Wd;

        asm volatile("cp.async.wait_group 0;" ::: "memory");
        __syncthreads();            // xa arrived; prev tile fully done

        // ---- restage weights when h changes (ordered by post-stage-X barrier) ----
        if(h!=cur_h){
            cur_h=h;
            const float* g1=W1g+h*4096;
            const float* g2=W2g+h*4096;
            #pragma unroll
            for(int i=0;i<4;++i){
                const int p=tid+i*TPB;
                const int n=p>>5, c0=(p&31)*2;
                uint32_t s[2];
                const float2 v1=*reinterpret_cast<const float2*>(g1+n*64+c0);
                split2pair(v1.x,v1.y,s);
                uint32_t a=sb+SM_W1+(n*XS+c0)*2;
                sts32(a,s[0]); sts32(a+WSPL,s[1]);
                w1f[n*65+c0]=v1.x; w1f[n*65+c0+1]=v1.y;
                const float2 v2=*reinterpret_cast<const float2*>(g2+n*64+c0);
                split2pair(v2.x,v2.y,s);
                a=sb+SM_W2+(n*XS+c0)*2;
                sts32(a,s[0]); sts32(a+WSPL,s[1]);
                w2f[n*65+c0]=v2.x; w2f[n*65+c0+1]=v2.y;
            }
            const float* g3=W3g+h*2048;
            #pragma unroll
            for(int i=0;i<2;++i){
                const int p=tid+i*TPB;
                const int n=p>>5, c0=(p&31)*2;
                uint32_t s[2];
                const float2 v=*reinterpret_cast<const float2*>(g3+n*64+c0);
                split2pair(v.x,v.y,s);
                const uint32_t a=sb+SM_W3+(n*XS+c0)*2;
                sts32(a,s[0]); sts32(a+W3SPL,s[1]);
                w3f[n*65+c0]=v.x; w3f[n*65+c0+1]=v.y;
            }
            const float* gr=Wr+(size_t)(h*K)*128;
            const int n=tid>>3, k=n>>1, o=n&1;
            #pragma unroll
            for(int j=0;j<4;++j){
                const int c=2*((tid&7)+j*8);
                const float va=gr[k*128+c*2+o];
                const float vb=gr[k*128+(c+1)*2+o];
                uint32_t s[2];
                split2pair(va,vb,s);
                const uint32_t a=sb+SM_WR+(n*XS+c)*2;
                sts32(a,s[0]); sts32(a+WSPL,s[1]);
            }
            if(tid<64){
                smf[SM_B1/4+tid]=b1g[h*64+tid];
                smf[SM_B2/4+tid]=b2g[h*64+tid];
                smf[SM_BR/4+tid]=br[h*64+tid];
            }
            if(tid<32) smf[SM_B3/4+tid]=b3g[h*32+tid];
        }

        // ---- stage X from xa: LDS -> 2 bf16 splits ----
        {
            if(tid==0) *sNF=0;
            const int px=tid&127, c0=(tid>>7)*16;
            #pragma unroll
            for(int j=0;j<8;++j){
                const int c=c0+2*j;
                const float va=xa[c*128+px];
                const float vb=xa[(c+1)*128+px];
                uint32_t s[2];
                split2pair(va,vb,s);
                const uint32_t a=sb+SM_X+(px*XS+c)*2;
                sts32(a,s[0]); sts32(a+XSPL,s[1]);
            }
        }
        __syncthreads();            // weights + X splits visible; xa consumed

        // ---- prefetch next tile's x (overlaps all compute below) ----
        if(t+1<t1){
            const int hb2=(t+1)/5, wt2=(t+1)-hb2*5, h2=hb2>>1, b2=hb2&1;
            const float* base=x+(size_t)b2*64*HW+(size_t)h2*Wd;
            #pragma unroll
            for(int i=0;i<4;++i){
                const int chunk=tid+i*TPB, c=chunk>>5, g=chunk&31;
                const int w=min(wt2*PXT+g*4, Wd-4);
                cp16(sb+SM_XA+(c*128+g*4)*4, base+(size_t)c*HW+w);
            }
            asm volatile("cp.async.commit_group;" ::: "memory");
        }

        // ---- L1 + Dr fused: Y0 = lrelu(X.W1^T+b1); Dr = X.Wr^T ----
        float Dr[4][4];
        {
            float D1[4][4];
            gemm3_dual(aX, bW1, bWR, D1, Dr);
            epi2(D1, smf+SM_B1/4, sb+SM_Y0, wm, wn, lane);
        }
        __syncthreads();

        // ---- L2: Y1 = lrelu(Y0.W2^T+b2) -> overlays X splits ----
        {
            float D2[4][4];
            gemm3(aY0, bW2, D2);
            epi2(D2, smf+SM_B2/4, sb+SM_X, wm, wn, lane);
        }
        __syncthreads();

        // ---- L3 (all warps, 8 classes each): top-2 partials ----
        {
            float D3[2][4];
            gemm3_n8(aX, bW3, D3);
            const float* b3s=smf+SM_B3/4;
            const int g=lane>>2, c2=2*(lane&3);
            const int n0=wn*8+c2;
            const float bv0=b3s[n0], bv1=b3s[n0+1];
            #pragma unroll
            for(int mt=0;mt<2;++mt){
                #pragma unroll
                for(int half=0;half<2;++half){
                    const float va=D3[mt][half*2]+bv0;
                    const float vb=D3[mt][half*2+1]+bv1;
                    float v1=(vb>va)?vb:va;
                    int   i1=(vb>va)?n0+1:n0;
                    float v2=(vb>va)?va:vb;
                    #pragma unroll
                    for(int m=1;m<=2;m<<=1){
                        const float u1=__shfl_xor_sync(0xFFFFFFFFu,v1,m);
                        const int   j1=__shfl_xor_sync(0xFFFFFFFFu,i1,m);
                        const float u2=__shfl_xor_sync(0xFFFFFFFFu,v2,m);
                        if(u1>v1 || (u1==v1 && j1<i1)){ v2=fmaxf(v1,u2); v1=u1; i1=j1; }
                        else { v2=fmaxf(u1,v2); }
                    }
                    if((lane&3)==0){
                        const int r=wm*32+mt*16+half*8+g;
                        sV1[wn*128+r]=v1; sV2[wn*128+r]=v2; sI1[wn*128+r]=i1;
                    }
                }
            }
        }
        // ---- spill Dr (f32) into freed Y0 region ----
        {
            float* dr=reinterpret_cast<float*>(smem+SM_DR);
            const int g=lane>>2, c2=2*(lane&3);
            #pragma unroll
            for(int mt=0;mt<2;++mt)
                #pragma unroll
                for(int nt=0;nt<2;++nt){
                    const int n0=wn*16+nt*8+c2;
                    const float* d=Dr[mt*2+nt];
                    *reinterpret_cast<float2*>(dr+(wm*32+mt*16+g)*DRS+n0)  =make_float2(d[0],d[1]);
                    *reinterpret_cast<float2*>(dr+(wm*32+mt*16+g+8)*DRS+n0)=make_float2(d[2],d[3]);
                }
        }
        __syncthreads();

        // ---- tail A: merge 4 top-2 partials, flag near-ties, write winners ----
        if(tid<128){
            const int px=tid, wc=w0+px;
            if(wc<Wd){
                float top1=-3.402823466e38f, sec=-3.402823466e38f; int bk=0;
                #pragma unroll
                for(int q=0;q<4;++q){
                    const float v1=sV1[q*128+px], v2=sV2[q*128+px];
                    const int   i1=sI1[q*128+px];
                    if(v1>top1){ sec=fmaxf(top1,v2); top1=v1; bk=i1; }
                    else       { sec=fmaxf(sec,v1); }
                }
                if(top1-sec < TAU){
                    const int f=atomicAdd(sNF,1);
                    sFL[f]=px;
                } else {
                    const float* dr=reinterpret_cast<const float*>(smem+SM_DR);
                    const float2 dv=*reinterpret_cast<const float2*>(dr+px*DRS+2*bk);
                    const float reg0=lrelu(dv.x+smf[SM_BR/4+2*bk]);
                    const float reg1=lrelu(dv.y+smf[SM_BR/4+2*bk+1]);
                    const int flat=h*K+bk;
                    out[pix_base+wc]      =((float)flat+reg0)*inv_k;
                    out[plane+pix_base+wc]=lrelu(reg1);
                }
            }
        }
        __syncthreads();

        // ---- tail B: exact fp32 recompute for flagged pixels ----
        {
            const int nF=*sNF;
            for(int f=warp; f<nF; f+=16){
                const int px=sFL[f];
                const int wc=w0+px;
                float* sw=scr+warp*128;         // [0:64) x/y1, [64:128) y0
                // load x from gmem (L2-hot)
                const float* xg=x+(size_t)b*64*HW+(size_t)h*Wd+wc;
                sw[lane]   =__ldg(xg+(size_t)lane*HW);
                sw[lane+32]=__ldg(xg+(size_t)(lane+32)*HW);
                __syncwarp();
                // L1 -> y0 in sw[64..127]
                #pragma unroll
                for(int r=0;r<2;++r){
                    const int o=lane+r*32;
                    float acc=smf[SM_B1/4+o];
                    const float* wr=w1f+o*65;
                    #pragma unroll
                    for(int c=0;c<64;++c) acc=fmaf(wr[c],sw[c],acc);
                    // defer store until all reads of sw[0..63]? lanes read all c -> must sync first
                    sw[64+o]=lrelu(acc);   // writes [64..127]; reads were [0..63] ✓ no overlap
                }
                __syncwarp();
                // L2 -> y1 overwrites sw[0..63]
                float y1v[2];
                #pragma unroll
                for(int r=0;r<2;++r){
                    const int o=lane+r*32;
                    float acc=smf[SM_B2/4+o];
                    const float* wr=w2f+o*65;
                    #pragma unroll
                    for(int c=0;c<64;++c) acc=fmaf(wr[c],sw[64+c],acc);
                    y1v[r]=lrelu(acc);
                }
                __syncwarp();
                sw[lane]=y1v[0]; sw[lane+32]=y1v[1];
                __syncwarp();
                // L3 + warp argmax (first-max)
                float v; int idx=lane;
                {
                    float acc=smf[SM_B3/4+lane];
                    const float* wr=w3f+lane*65;
                    #pragma unroll
                    for(int c=0;c<64;++c) acc=fmaf(wr[c],sw[c],acc);
                    v=acc;
                }
                #pragma unroll
                for(int m=16;m>=1;m>>=1){
                    const float ov=__shfl_xor_sync(0xFFFFFFFFu,v,m);
                    const int   oi=__shfl_xor_sync(0xFFFFFFFFu,idx,m);
                    if(ov>v || (ov==v && oi<idx)){ v=ov; idx=oi; }
                }
                if(lane==0){
                    const int bk=idx;
                    const float* dr=reinterpret_cast<const float*>(smem+SM_DR);
                    const float2 dv=*reinterpret_cast<const float2*>(dr+px*DRS+2*bk);
                    const float reg0=lrelu(dv.x+smf[SM_BR/4+2*bk]);
                    const float reg1=lrelu(dv.y+smf[SM_BR/4+2*bk+1]);
                    const int flat=h*K+bk;
                    out[pix_base+wc]      =((float)flat+reg0)*inv_k;
                    out[plane+pix_base+wc]=lrelu(reg1);
                }
            }
        }
    }
}

extern "C" void kernel_launch(void* const* d_in, const int* in_sizes, int n_in,
                              void* d_out, int out_size)
{
    const float* x =(const float*)d_in[0];
    const float* W1=(const float*)d_in[1];
    const float* b1=(const float*)d_in[2];
    const float* W2=(const float*)d_in[3];
    const float* b2=(const float*)d_in[4];
    const float* W3=(const float*)d_in[5];
    const float* b3=(const float*)d_in[6];
    const float* Wr=(const float*)d_in[7];
    const float* br=(const float*)d_in[8];
    float* out=(float*)d_out;

    cudaFuncSetAttribute(reg1stage_emu,
                         cudaFuncAttributeMaxDynamicSharedMemorySize, SMEM_BYTES);
    reg1stage_emu<<<NSM,TPB,SMEM_BYTES>>>(x,W1,b1,W2,b2,W3,b3,Wr,br,out);
}